// round 15
// baseline (speedup 1.0000x reference)
#include <cuda_runtime.h>
#include <cstdint>
#include <cstddef>

// ---------------------------------------------------------------------------
// Problem constants
// ---------------------------------------------------------------------------
#define BATCH   64
#define TSTEPS  600
#define NMEL    80
#define ENCPOS  544
#define PRE     256
#define RNN     1024
#define XK      800                 // PRE + ENCPOS
#define NG      4096                // 4*RNN
#define NROWS   (TSTEPS*BATCH)      // 38400
#define PROJK   1568
#define NCTA    128

// ---------------------------------------------------------------------------
// Static device scratch (allocation-free rule)
// ---------------------------------------------------------------------------
__device__ float d_X [(size_t)NROWS * XK];     // concat(prenet, dur)
__device__ float d_G1[(size_t)NROWS * NG];     // x @ W_ih1^T + b_ih1 + b_hh1
__device__ float d_PD[(size_t)NROWS * NMEL];   // dur-part of projection + bias
__device__ float d_h1[2][BATCH * RNN];
__device__ float d_h2[2][BATCH * RNN];
__device__ float d_c1[BATCH * RNN];
__device__ float d_c2[BATCH * RNN];
__device__ unsigned g_bar_count;
__device__ volatile unsigned g_bar_gen;

// ---------------------------------------------------------------------------
// Threefry-2x32 (verified bit-exact vs published test vector)
// ---------------------------------------------------------------------------
__host__ __device__ __forceinline__ void tf2x32(uint32_t k0, uint32_t k1,
                                                uint32_t& x0, uint32_t& x1) {
    uint32_t ks2 = k0 ^ k1 ^ 0x1BD11BDAu;
#define TF_ROT(v,d) (((v) << (d)) | ((v) >> (32 - (d))))
#define TF_RND(r) { x0 += x1; x1 = TF_ROT(x1, r); x1 ^= x0; }
    x0 += k0; x1 += k1;
    TF_RND(13) TF_RND(15) TF_RND(26) TF_RND(6)
    x0 += k1;  x1 += ks2 + 1u;
    TF_RND(17) TF_RND(29) TF_RND(16) TF_RND(24)
    x0 += ks2; x1 += k0 + 2u;
    TF_RND(13) TF_RND(15) TF_RND(26) TF_RND(6)
    x0 += k0;  x1 += k1 + 3u;
    TF_RND(17) TF_RND(29) TF_RND(16) TF_RND(24)
    x0 += k1;  x1 += ks2 + 4u;
    TF_RND(13) TF_RND(15) TF_RND(26) TF_RND(6)
    x0 += ks2; x1 += k0 + 5u;
#undef TF_RND
#undef TF_ROT
}

// x64-harness partitionable semantics: f64 uniform consumes 64-bit bits
// bits64 = (y0<<32)|y1 of block (0, idx);  u < 0.5  <=>  MSB(bits64)==0
//  <=>  MSB(y0)==0  <=>  keep.
__device__ __forceinline__ bool keep_mask(uint32_t k0, uint32_t k1, uint32_t idx) {
    uint32_t x0 = 0u, x1 = idx;
    tf2x32(k0, k1, x0, x1);
    return ((x0 >> 31) == 0u);
}

__device__ __forceinline__ float sigf(float x) { return 1.0f / (1.0f + expf(-x)); }

// ---------------------------------------------------------------------------
// Prenet: 2x (linear + relu + exact-JAX dropout p=0.5) -> d_X[:, 0:256]
// grid (8, 600): block handles 8 batch rows of one timestep
// ---------------------------------------------------------------------------
__global__ void __launch_bounds__(256) prenet_kernel(
        const float* __restrict__ dec,      // [64, 80, 600]
        const float* __restrict__ Wp1,      // [256, 80]
        const float* __restrict__ Wp2,      // [256, 256]
        uint32_t k1x, uint32_t k1y, uint32_t k2x, uint32_t k2y) {
    __shared__ __align__(16) float xs[8][80];
    __shared__ __align__(16) float y1s[8][256];
    const int t   = blockIdx.y;
    const int bg  = blockIdx.x;
    const int tid = threadIdx.x;

    if (t == 0) {
        for (int p = tid; p < 8 * 80; p += 256) ((float*)xs)[p] = 0.0f;
    } else {
        for (int p = tid; p < 8 * 80; p += 256) {
            int r = p / 80, m = p % 80;
            xs[r][m] = dec[(size_t)(bg * 8 + r) * 48000 + m * 600 + (t - 1)];
        }
    }
    __syncthreads();

    const int j = tid;              // output feature 0..255
    float acc[8];
#pragma unroll
    for (int r = 0; r < 8; r++) acc[r] = 0.0f;
#pragma unroll
    for (int m = 0; m < 80; m += 4) {
        float4 w = *(const float4*)&Wp1[j * 80 + m];
#pragma unroll
        for (int r = 0; r < 8; r++) {
            float4 x = *(const float4*)&xs[r][m];
            acc[r] += w.x * x.x + w.y * x.y + w.z * x.z + w.w * x.w;
        }
    }
#pragma unroll
    for (int r = 0; r < 8; r++) {
        float v = fmaxf(acc[r], 0.0f);
        uint32_t idx = (uint32_t)(t * 64 + bg * 8 + r) * 256u + (uint32_t)j;
        y1s[r][j] = keep_mask(k1x, k1y, idx) ? 2.0f * v : 0.0f;
    }
    __syncthreads();

    float acc2[8];
#pragma unroll
    for (int r = 0; r < 8; r++) acc2[r] = 0.0f;
#pragma unroll 4
    for (int k = 0; k < 256; k += 4) {
        float4 w = *(const float4*)&Wp2[j * 256 + k];
#pragma unroll
        for (int r = 0; r < 8; r++) {
            float4 x = *(const float4*)&y1s[r][k];
            acc2[r] += w.x * x.x + w.y * x.y + w.z * x.z + w.w * x.w;
        }
    }
#pragma unroll
    for (int r = 0; r < 8; r++) {
        float v = fmaxf(acc2[r], 0.0f);
        int b = bg * 8 + r;
        uint32_t idx = (uint32_t)(t * 64 + b) * 256u + (uint32_t)j;
        v = keep_mask(k2x, k2y, idx) ? 2.0f * v : 0.0f;
        d_X[(size_t)(t * 64 + b) * XK + j] = v;
    }
}

// ---------------------------------------------------------------------------
// d_X[:, 256:800] = duration_outputs (b, t, :)
// ---------------------------------------------------------------------------
__global__ void build_x_kernel(const float* __restrict__ dur) {
    int idx = blockIdx.x * blockDim.x + threadIdx.x;
    if (idx >= NROWS * ENCPOS) return;
    int row = idx / ENCPOS, k = idx - row * ENCPOS;
    int t = row / BATCH, b = row - t * BATCH;
    d_X[(size_t)row * XK + PRE + k] =
        dur[(size_t)b * (TSTEPS * ENCPOS) + t * ENCPOS + k];
}

// ---------------------------------------------------------------------------
// d_PD[row][m] = dur(row) . Wproj[m, 1024:1568] + bproj[m]
// ---------------------------------------------------------------------------
__global__ void projdur_kernel(const float* __restrict__ dur,
                               const float* __restrict__ Wproj,
                               const float* __restrict__ bproj) {
    int gid = blockIdx.x * blockDim.x + threadIdx.x;
    if (gid >= NROWS * NMEL) return;
    int row = gid / NMEL, m = gid - row * NMEL;
    int t = row / BATCH, b = row - t * BATCH;
    const float* xr = dur + (size_t)b * (TSTEPS * ENCPOS) + t * ENCPOS;
    const float* wr = Wproj + (size_t)m * PROJK + RNN;
    float a0 = 0.f, a1 = 0.f, a2 = 0.f, a3 = 0.f;
#pragma unroll 4
    for (int k = 0; k < ENCPOS; k += 4) {
        float4 x = *(const float4*)&xr[k];
        float4 w = *(const float4*)&wr[k];
        a0 += x.x * w.x; a1 += x.y * w.y; a2 += x.z * w.z; a3 += x.w * w.w;
    }
    d_PD[gid] = bproj[m] + ((a0 + a1) + (a2 + a3));
}

// ---------------------------------------------------------------------------
// d_G1[38400,4096] = d_X @ W_ih1^T + (b_ih1 + b_hh1)
// 128x128 tiles, 8x8 microtile, BK=16.  (300 x 32 x 50 — no tails)
// ---------------------------------------------------------------------------
__global__ void __launch_bounds__(256) gemm_g1_kernel(
        const float* __restrict__ W,        // [4096, 800]
        const float* __restrict__ bih, const float* __restrict__ bhh) {
    __shared__ __align__(16) float As[16][132];
    __shared__ __align__(16) float Bs[16][132];
    const int tid = threadIdx.x;
    const int m0 = blockIdx.y * 128, n0 = blockIdx.x * 128;
    const int tx = tid & 15, ty = tid >> 4;

    float acc[8][8];
#pragma unroll
    for (int i = 0; i < 8; i++)
#pragma unroll
        for (int jj = 0; jj < 8; jj++) acc[i][jj] = 0.0f;

    for (int k0 = 0; k0 < XK; k0 += 16) {
#pragma unroll
        for (int i = 0; i < 2; i++) {
            int q = tid * 2 + i;                 // 0..511
            int mm = q >> 2, kv = (q & 3) << 2;
            float4 va = *(const float4*)&d_X[(size_t)(m0 + mm) * XK + k0 + kv];
            As[kv + 0][mm] = va.x; As[kv + 1][mm] = va.y;
            As[kv + 2][mm] = va.z; As[kv + 3][mm] = va.w;
            float4 vb = *(const float4*)&W[(size_t)(n0 + mm) * XK + k0 + kv];
            Bs[kv + 0][mm] = vb.x; Bs[kv + 1][mm] = vb.y;
            Bs[kv + 2][mm] = vb.z; Bs[kv + 3][mm] = vb.w;
        }
        __syncthreads();
#pragma unroll
        for (int k = 0; k < 16; k++) {
            float a[8], b[8];
            *(float4*)&a[0] = *(const float4*)&As[k][ty * 8];
            *(float4*)&a[4] = *(const float4*)&As[k][ty * 8 + 4];
            *(float4*)&b[0] = *(const float4*)&Bs[k][tx * 8];
            *(float4*)&b[4] = *(const float4*)&Bs[k][tx * 8 + 4];
#pragma unroll
            for (int i = 0; i < 8; i++)
#pragma unroll
                for (int jj = 0; jj < 8; jj++)
                    acc[i][jj] = fmaf(a[i], b[jj], acc[i][jj]);
        }
        __syncthreads();
    }
#pragma unroll
    for (int i = 0; i < 8; i++) {
        int row = m0 + ty * 8 + i;
#pragma unroll
        for (int jj = 0; jj < 8; jj++) {
            int n = n0 + tx * 8 + jj;
            d_G1[(size_t)row * NG + n] = acc[i][jj] + bih[n] + bhh[n];
        }
    }
}

// ---------------------------------------------------------------------------
// Sequential persistent kernel: 600 steps, 2 grid barriers per step
// ---------------------------------------------------------------------------
__device__ __forceinline__ void grid_barrier() {
    __syncthreads();
    if (threadIdx.x == 0) {
        __threadfence();
        unsigned gen = g_bar_gen;
        if (atomicAdd(&g_bar_count, 1u) == NCTA - 1u) {
            atomicExch(&g_bar_count, 0u);
            __threadfence();
            g_bar_gen = gen + 1u;
        } else {
            while (g_bar_gen == gen) { }
        }
        __threadfence();
    }
    __syncthreads();
}

// acc[8] += A[64,1024] slab against this CTA's 32 weight rows.
__device__ __forceinline__ void gemm_acc(const float* __restrict__ A,
                                         const float* __restrict__ W,
                                         size_t woff, float acc[8],
                                         float (*As)[68], float (*Bs)[36]) {
    const int tid = threadIdx.x;
    const int tx = tid & 31, ty = tid >> 5;
    const int lb = tid >> 2;             // 0..63  (A-load batch)
    const int kq = (tid & 3) << 2;       // k-quarter
    for (int k0 = 0; k0 < 1024; k0 += 16) {
        float4 va = *(const float4*)&A[lb * 1024 + k0 + kq];
        As[kq + 0][lb] = va.x; As[kq + 1][lb] = va.y;
        As[kq + 2][lb] = va.z; As[kq + 3][lb] = va.w;
        if (tid < 128) {
            int lr = tid >> 2;           // 0..31 (B-load row)
            float4 wv = *(const float4*)&W[woff + k0 + kq];
            Bs[kq + 0][lr] = wv.x; Bs[kq + 1][lr] = wv.y;
            Bs[kq + 2][lr] = wv.z; Bs[kq + 3][lr] = wv.w;
        }
        __syncthreads();
#pragma unroll
        for (int k = 0; k < 16; k++) {
            float bv = Bs[k][tx];
            float4 a0 = *(const float4*)&As[k][ty * 8];
            float4 a1 = *(const float4*)&As[k][ty * 8 + 4];
            acc[0] = fmaf(a0.x, bv, acc[0]);
            acc[1] = fmaf(a0.y, bv, acc[1]);
            acc[2] = fmaf(a0.z, bv, acc[2]);
            acc[3] = fmaf(a0.w, bv, acc[3]);
            acc[4] = fmaf(a1.x, bv, acc[4]);
            acc[5] = fmaf(a1.y, bv, acc[5]);
            acc[6] = fmaf(a1.z, bv, acc[6]);
            acc[7] = fmaf(a1.w, bv, acc[7]);
        }
        __syncthreads();
    }
}

// Projection of one finished step: 5120 outputs, 4 threads each (shfl reduce)
__device__ __forceinline__ void do_proj(int outT, const float* __restrict__ h2b,
                                        const float* __restrict__ Wproj,
                                        float* __restrict__ out) {
    const int tid = threadIdx.x;
    if (tid >= 160) return;
    int o = blockIdx.x * 40 + (tid >> 2);
    int part = tid & 3;
    int b = o / 80, m = o - b * 80;
    const float* hp = h2b + b * 1024 + part * 256;
    const float* wp = Wproj + (size_t)m * PROJK + part * 256;
    float v = 0.f, v2 = 0.f;
#pragma unroll 8
    for (int k = 0; k < 256; k += 8) {
        float4 h4 = *(const float4*)&hp[k];     float4 w4 = *(const float4*)&wp[k];
        float4 h5 = *(const float4*)&hp[k + 4]; float4 w5 = *(const float4*)&wp[k + 4];
        v  += h4.x * w4.x + h4.y * w4.y + h4.z * w4.z + h4.w * w4.w;
        v2 += h5.x * w5.x + h5.y * w5.y + h5.z * w5.z + h5.w * w5.w;
    }
    v += v2;
    v += __shfl_xor_sync(0xffffffffu, v, 1);
    v += __shfl_xor_sync(0xffffffffu, v, 2);
    if (part == 0)
        out[(size_t)(b * 80 + m) * 600 + outT] =
            v + d_PD[((size_t)outT * 64 + b) * 80 + m];
}

__global__ void __launch_bounds__(256, 1) seq_kernel(
        const float* __restrict__ Whh1,
        const float* __restrict__ Wih2,
        const float* __restrict__ Whh2,
        const float* __restrict__ bih2,
        const float* __restrict__ bhh2,
        const float* __restrict__ Wproj,
        float* __restrict__ out) {
    __shared__ float As[16][68];
    __shared__ float Bs[16][36];
    __shared__ float Gs[32][65];

    const int tid = threadIdx.x;
    const int cta = blockIdx.x;
    const int c0 = cta * 8;
    const int tx = tid & 31, ty = tid >> 5;
    const int wrow = ((tx >> 3) << 10) + c0 + (tx & 7);   // gate col = weight row
    size_t woff = 0;
    if (tid < 128) {
        int lr = tid >> 2;
        woff = (size_t)(((lr >> 3) << 10) + c0 + (lr & 7)) * 1024;
    }
    const float bias2 = bih2[wrow] + bhh2[wrow];

    // zero initial state
    for (int i = cta * 256 + tid; i < BATCH * RNN; i += NCTA * 256) {
        d_h1[0][i] = 0.f; d_h2[0][i] = 0.f; d_c1[i] = 0.f; d_c2[i] = 0.f;
    }
    grid_barrier();

    for (int t = 0; t < TSTEPS; t++) {
        const int pb = t & 1, nb = pb ^ 1;

        if (t > 0) do_proj(t - 1, d_h2[pb], Wproj, out);

        // ---- LSTM1: gates = G1[t] + h1_prev @ Whh1^T ----
        float acc[8];
#pragma unroll
        for (int r = 0; r < 8; r++) acc[r] = 0.f;
        gemm_acc(d_h1[pb], Whh1, woff, acc, As, Bs);
        {
            const float* g1p = d_G1 + (size_t)t * 64 * NG;
#pragma unroll
            for (int r = 0; r < 8; r++) {
                int b = ty * 8 + r;
                Gs[tx][b] = acc[r] + g1p[(size_t)b * NG + wrow];
            }
        }
        __syncthreads();
#pragma unroll
        for (int s = 0; s < 2; s++) {
            int id = tid + s * 256;
            int uc = id >> 6, b = id & 63;
            float gi = Gs[uc][b],      gf = Gs[8 + uc][b];
            float gg = Gs[16 + uc][b], go = Gs[24 + uc][b];
            int ci = b * 1024 + c0 + uc;
            float c = d_c1[ci];
            float cn = sigf(gf) * c + sigf(gi) * tanhf(gg);
            d_c1[ci] = cn;
            d_h1[nb][ci] = sigf(go) * tanhf(cn);
        }
        grid_barrier();

        // ---- LSTM2: gates = h1 @ Wih2^T + h2_prev @ Whh2^T + b ----
#pragma unroll
        for (int r = 0; r < 8; r++) acc[r] = 0.f;
        gemm_acc(d_h1[nb], Wih2, woff, acc, As, Bs);
        gemm_acc(d_h2[pb], Whh2, woff, acc, As, Bs);
#pragma unroll
        for (int r = 0; r < 8; r++) {
            int b = ty * 8 + r;
            Gs[tx][b] = acc[r] + bias2;
        }
        __syncthreads();
#pragma unroll
        for (int s = 0; s < 2; s++) {
            int id = tid + s * 256;
            int uc = id >> 6, b = id & 63;
            float gi = Gs[uc][b],      gf = Gs[8 + uc][b];
            float gg = Gs[16 + uc][b], go = Gs[24 + uc][b];
            int ci = b * 1024 + c0 + uc;
            float c = d_c2[ci];
            float cn = sigf(gf) * c + sigf(gi) * tanhf(gg);
            d_c2[ci] = cn;
            d_h2[nb][ci] = sigf(go) * tanhf(cn);
        }
        grid_barrier();
    }

    // final step's projection (h2(599) lives in buffer (599&1)^1 = 0)
    do_proj(TSTEPS - 1, d_h2[0], Wproj, out);
}

// ---------------------------------------------------------------------------
// Launch
// ---------------------------------------------------------------------------
extern "C" void kernel_launch(void* const* d_in, const int* in_sizes, int n_in,
                              void* d_out, int out_size) {
    (void)in_sizes; (void)n_in; (void)out_size;
    const float* dur   = (const float*)d_in[0];
    const float* dec   = (const float*)d_in[1];
    // d_in[2] = memory_lengths (unused by reference)
    const float* Wp1   = (const float*)d_in[3];
    const float* Wp2   = (const float*)d_in[4];
    const float* Wih1  = (const float*)d_in[5];
    const float* Whh1  = (const float*)d_in[6];
    const float* bih1  = (const float*)d_in[7];
    const float* bhh1  = (const float*)d_in[8];
    const float* Wih2  = (const float*)d_in[9];
    const float* Whh2  = (const float*)d_in[10];
    const float* bih2  = (const float*)d_in[11];
    const float* bhh2  = (const float*)d_in[12];
    const float* Wproj = (const float*)d_in[13];
    const float* bproj = (const float*)d_in[14];
    float* out = (float*)d_out;

    // Partitionable (foldlike) split of jax.random.key(42) = (0, 42):
    // child i = full threefry block with counter (0, i).
    uint32_t d1a = 0u, d1b = 0u; tf2x32(0u, 42u, d1a, d1b);   // child 0
    uint32_t d2a = 0u, d2b = 1u; tf2x32(0u, 42u, d2a, d2b);   // child 1

    prenet_kernel<<<dim3(8, 600), 256>>>(dec, Wp1, Wp2, d1a, d1b, d2a, d2b);
    build_x_kernel<<<(NROWS * ENCPOS + 255) / 256, 256>>>(dur);
    projdur_kernel<<<(NROWS * NMEL + 255) / 256, 256>>>(dur, Wproj, bproj);
    gemm_g1_kernel<<<dim3(NG / 128, NROWS / 128), 256>>>(Wih1, bih1, bhh1);
    seq_kernel<<<NCTA, 256>>>(Whh1, Wih2, Whh2, bih2, bhh2, Wproj, out);
}

// round 17
// speedup vs baseline: 2.7153x; 2.7153x over previous
#include <cuda_runtime.h>
#include <cstdint>
#include <cstddef>

// ---------------------------------------------------------------------------
// Problem constants
// ---------------------------------------------------------------------------
#define BATCH   64
#define TSTEPS  600
#define NMEL    80
#define ENCPOS  544
#define PRE     256
#define RNN     1024
#define XK      800                 // PRE + ENCPOS
#define NG      4096                // 4*RNN
#define NROWS   (TSTEPS*BATCH)      // 38400
#define PROJK   1568
#define NCTA    128

// seq pipeline geometry
#define ARS     68                  // padded row stride (floats) for 64-wide slabs
#define SLABF   (64*ARS + 32*ARS)   // floats per stage (A 64xK64 + B 32xK64)
#define SEQ_SMEM_BYTES ((3*SLABF + 32*65)*4)

// ---------------------------------------------------------------------------
// Static device scratch (allocation-free rule)
// ---------------------------------------------------------------------------
__device__ float d_X [(size_t)NROWS * XK];     // concat(prenet, dur)
__device__ float d_G1[(size_t)NROWS * NG];     // x @ W_ih1^T + b_ih1 + b_hh1
__device__ float d_PD[(size_t)NROWS * NMEL];   // dur-part of projection + bias
__device__ float d_h1[2][BATCH * RNN];
__device__ float d_h2[2][BATCH * RNN];
__device__ float d_c1[BATCH * RNN];
__device__ float d_c2[BATCH * RNN];
__device__ unsigned g_bar_count;
__device__ volatile unsigned g_bar_gen;

// ---------------------------------------------------------------------------
// Threefry-2x32 (bit-exact) + x64-mode dropout mask (PASSING convention)
// ---------------------------------------------------------------------------
__host__ __device__ __forceinline__ void tf2x32(uint32_t k0, uint32_t k1,
                                                uint32_t& x0, uint32_t& x1) {
    uint32_t ks2 = k0 ^ k1 ^ 0x1BD11BDAu;
#define TF_ROT(v,d) (((v) << (d)) | ((v) >> (32 - (d))))
#define TF_RND(r) { x0 += x1; x1 = TF_ROT(x1, r); x1 ^= x0; }
    x0 += k0; x1 += k1;
    TF_RND(13) TF_RND(15) TF_RND(26) TF_RND(6)
    x0 += k1;  x1 += ks2 + 1u;
    TF_RND(17) TF_RND(29) TF_RND(16) TF_RND(24)
    x0 += ks2; x1 += k0 + 2u;
    TF_RND(13) TF_RND(15) TF_RND(26) TF_RND(6)
    x0 += k0;  x1 += k1 + 3u;
    TF_RND(17) TF_RND(29) TF_RND(16) TF_RND(24)
    x0 += k1;  x1 += ks2 + 4u;
    TF_RND(13) TF_RND(15) TF_RND(26) TF_RND(6)
    x0 += ks2; x1 += k0 + 5u;
#undef TF_RND
#undef TF_ROT
}

__device__ __forceinline__ bool keep_mask(uint32_t k0, uint32_t k1, uint32_t idx) {
    uint32_t x0 = 0u, x1 = idx;
    tf2x32(k0, k1, x0, x1);
    return ((x0 >> 31) == 0u);
}

__device__ __forceinline__ float sigf(float x) { return 1.0f / (1.0f + expf(-x)); }

// ---------------------------------------------------------------------------
// mma / cp.async helpers
// ---------------------------------------------------------------------------
__device__ __forceinline__ uint32_t cvt_tf32(float x) {
    uint32_t r;
    asm("cvt.rna.tf32.f32 %0, %1;" : "=r"(r) : "f"(x));
    return r;
}

__device__ __forceinline__ void mma_tf32(float& d0, float& d1, float& d2, float& d3,
                                         uint32_t a0, uint32_t a1, uint32_t a2, uint32_t a3,
                                         uint32_t b0, uint32_t b1) {
    asm volatile(
        "mma.sync.aligned.m16n8k8.row.col.f32.tf32.tf32.f32 "
        "{%0,%1,%2,%3}, {%4,%5,%6,%7}, {%8,%9}, {%0,%1,%2,%3};\n"
        : "+f"(d0), "+f"(d1), "+f"(d2), "+f"(d3)
        : "r"(a0), "r"(a1), "r"(a2), "r"(a3), "r"(b0), "r"(b1));
}

__device__ __forceinline__ uint32_t saddr(const void* p) {
    return (uint32_t)__cvta_generic_to_shared(p);
}
__device__ __forceinline__ void cp16(uint32_t sa, const float* g) {
    asm volatile("cp.async.cg.shared.global [%0], [%1], 16;\n" :: "r"(sa), "l"(g));
}
#define CP_COMMIT() asm volatile("cp.async.commit_group;\n")

// ---------------------------------------------------------------------------
// Prenet (unchanged — carries the passing numerics)
// ---------------------------------------------------------------------------
__global__ void __launch_bounds__(256) prenet_kernel(
        const float* __restrict__ dec,
        const float* __restrict__ Wp1,
        const float* __restrict__ Wp2,
        uint32_t k1x, uint32_t k1y, uint32_t k2x, uint32_t k2y) {
    __shared__ __align__(16) float xs[8][80];
    __shared__ __align__(16) float y1s[8][256];
    const int t   = blockIdx.y;
    const int bg  = blockIdx.x;
    const int tid = threadIdx.x;

    if (t == 0) {
        for (int p = tid; p < 8 * 80; p += 256) ((float*)xs)[p] = 0.0f;
    } else {
        for (int p = tid; p < 8 * 80; p += 256) {
            int r = p / 80, m = p % 80;
            xs[r][m] = dec[(size_t)(bg * 8 + r) * 48000 + m * 600 + (t - 1)];
        }
    }
    __syncthreads();

    const int j = tid;
    float acc[8];
#pragma unroll
    for (int r = 0; r < 8; r++) acc[r] = 0.0f;
#pragma unroll
    for (int m = 0; m < 80; m += 4) {
        float4 w = *(const float4*)&Wp1[j * 80 + m];
#pragma unroll
        for (int r = 0; r < 8; r++) {
            float4 x = *(const float4*)&xs[r][m];
            acc[r] += w.x * x.x + w.y * x.y + w.z * x.z + w.w * x.w;
        }
    }
#pragma unroll
    for (int r = 0; r < 8; r++) {
        float v = fmaxf(acc[r], 0.0f);
        uint32_t idx = (uint32_t)(t * 64 + bg * 8 + r) * 256u + (uint32_t)j;
        y1s[r][j] = keep_mask(k1x, k1y, idx) ? 2.0f * v : 0.0f;
    }
    __syncthreads();

    float acc2[8];
#pragma unroll
    for (int r = 0; r < 8; r++) acc2[r] = 0.0f;
#pragma unroll 4
    for (int k = 0; k < 256; k += 4) {
        float4 w = *(const float4*)&Wp2[j * 256 + k];
#pragma unroll
        for (int r = 0; r < 8; r++) {
            float4 x = *(const float4*)&y1s[r][k];
            acc2[r] += w.x * x.x + w.y * x.y + w.z * x.z + w.w * x.w;
        }
    }
#pragma unroll
    for (int r = 0; r < 8; r++) {
        float v = fmaxf(acc2[r], 0.0f);
        int b = bg * 8 + r;
        uint32_t idx = (uint32_t)(t * 64 + b) * 256u + (uint32_t)j;
        v = keep_mask(k2x, k2y, idx) ? 2.0f * v : 0.0f;
        d_X[(size_t)(t * 64 + b) * XK + j] = v;
    }
}

// ---------------------------------------------------------------------------
// d_X[:, 256:800] = duration_outputs (b, t, :)
// ---------------------------------------------------------------------------
__global__ void build_x_kernel(const float* __restrict__ dur) {
    int idx = blockIdx.x * blockDim.x + threadIdx.x;
    if (idx >= NROWS * ENCPOS) return;
    int row = idx / ENCPOS, k = idx - row * ENCPOS;
    int t = row / BATCH, b = row - t * BATCH;
    d_X[(size_t)row * XK + PRE + k] =
        dur[(size_t)b * (TSTEPS * ENCPOS) + t * ENCPOS + k];
}

// ---------------------------------------------------------------------------
// d_PD[row][m] = dur(row) . Wproj[m, 1024:1568] + bproj[m]
// ---------------------------------------------------------------------------
__global__ void projdur_kernel(const float* __restrict__ dur,
                               const float* __restrict__ Wproj,
                               const float* __restrict__ bproj) {
    int gid = blockIdx.x * blockDim.x + threadIdx.x;
    if (gid >= NROWS * NMEL) return;
    int row = gid / NMEL, m = gid - row * NMEL;
    int t = row / BATCH, b = row - t * BATCH;
    const float* xr = dur + (size_t)b * (TSTEPS * ENCPOS) + t * ENCPOS;
    const float* wr = Wproj + (size_t)m * PROJK + RNN;
    float a0 = 0.f, a1 = 0.f, a2 = 0.f, a3 = 0.f;
#pragma unroll 4
    for (int k = 0; k < ENCPOS; k += 4) {
        float4 x = *(const float4*)&xr[k];
        float4 w = *(const float4*)&wr[k];
        a0 += x.x * w.x; a1 += x.y * w.y; a2 += x.z * w.z; a3 += x.w * w.w;
    }
    d_PD[gid] = bproj[m] + ((a0 + a1) + (a2 + a3));
}

// ---------------------------------------------------------------------------
// G1 GEMM via tf32 mma: d_G1[38400,4096] = X @ W_ih1^T + b
// BM=128, BN=128, BK=16, 8 warps, each 64x32 via m16n8k8; 2-stage cp.async
// ---------------------------------------------------------------------------
__global__ void __launch_bounds__(256) gemm_g1_mma(
        const float* __restrict__ W,
        const float* __restrict__ bih, const float* __restrict__ bhh) {
    __shared__ __align__(16) float As[2][128 * 20];
    __shared__ __align__(16) float Bs[2][128 * 20];
    const int tid  = threadIdx.x;
    const int lane = tid & 31, w = tid >> 5;
    const int gi = lane >> 2, ti = lane & 3;
    const int m0blk = blockIdx.y * 128, n0blk = blockIdx.x * 128;
    const int m0 = (w >> 2) * 64, n0 = (w & 3) * 32;

    float acc[4][4][4];
#pragma unroll
    for (int mt = 0; mt < 4; mt++)
#pragma unroll
        for (int nt = 0; nt < 4; nt++)
#pragma unroll
            for (int d = 0; d < 4; d++) acc[mt][nt][d] = 0.0f;

    float bsum[4][2];
#pragma unroll
    for (int nt = 0; nt < 4; nt++)
#pragma unroll
        for (int jv = 0; jv < 2; jv++) {
            int col = n0blk + n0 + nt * 8 + 2 * ti + jv;
            bsum[nt][jv] = bih[col] + bhh[col];
        }

    auto issue = [&](int st, int k0) {
#pragma unroll
        for (int i = 0; i < 2; i++) {
            int ch = tid + 256 * i;
            int r = ch >> 2, cq = (ch & 3) * 4;
            cp16(saddr(&As[st][r * 20 + cq]), d_X + (size_t)(m0blk + r) * XK + k0 + cq);
            cp16(saddr(&Bs[st][r * 20 + cq]), W   + (size_t)(n0blk + r) * XK + k0 + cq);
        }
        CP_COMMIT();
    };

    auto compute = [&](int st) {
#pragma unroll
        for (int kk = 0; kk < 16; kk += 8) {
            uint32_t af[4][4];
#pragma unroll
            for (int mt = 0; mt < 4; mt++) {
                const float* ap = &As[st][(m0 + mt * 16 + gi) * 20 + kk + ti];
                af[mt][0] = cvt_tf32(ap[0]);
                af[mt][1] = cvt_tf32(ap[8 * 20]);
                af[mt][2] = cvt_tf32(ap[4]);
                af[mt][3] = cvt_tf32(ap[8 * 20 + 4]);
            }
#pragma unroll
            for (int nt = 0; nt < 4; nt++) {
                const float* bp = &Bs[st][(n0 + nt * 8 + gi) * 20 + kk + ti];
                uint32_t b0 = cvt_tf32(bp[0]), b1 = cvt_tf32(bp[4]);
#pragma unroll
                for (int mt = 0; mt < 4; mt++)
                    mma_tf32(acc[mt][nt][0], acc[mt][nt][1], acc[mt][nt][2], acc[mt][nt][3],
                             af[mt][0], af[mt][1], af[mt][2], af[mt][3], b0, b1);
            }
        }
    };

    issue(0, 0);
    for (int i = 0; i < 50; i++) {
        if (i + 1 < 50) {
            issue((i + 1) & 1, (i + 1) * 16);
            asm volatile("cp.async.wait_group 1;\n");
        } else {
            asm volatile("cp.async.wait_group 0;\n");
        }
        __syncthreads();
        compute(i & 1);
        __syncthreads();
    }

#pragma unroll
    for (int mt = 0; mt < 4; mt++)
#pragma unroll
        for (int nt = 0; nt < 4; nt++) {
            int col = n0blk + n0 + nt * 8 + 2 * ti;
            int r0  = m0blk + m0 + mt * 16 + gi;
            float2 v0 = make_float2(acc[mt][nt][0] + bsum[nt][0],
                                    acc[mt][nt][1] + bsum[nt][1]);
            float2 v1 = make_float2(acc[mt][nt][2] + bsum[nt][0],
                                    acc[mt][nt][3] + bsum[nt][1]);
            *(float2*)&d_G1[(size_t)r0 * NG + col]       = v0;
            *(float2*)&d_G1[(size_t)(r0 + 8) * NG + col] = v1;
        }
}

// ---------------------------------------------------------------------------
// Grid barrier
// ---------------------------------------------------------------------------
__device__ __forceinline__ void grid_barrier() {
    __syncthreads();
    if (threadIdx.x == 0) {
        __threadfence();
        unsigned gen = g_bar_gen;
        if (atomicAdd(&g_bar_count, 1u) == NCTA - 1u) {
            atomicExch(&g_bar_count, 0u);
            __threadfence();
            g_bar_gen = gen + 1u;
        } else {
            while (g_bar_gen == gen) { }
        }
        __threadfence();
    }
    __syncthreads();
}

// Projection of one finished step (scalar; 160 threads)
__device__ __forceinline__ void do_proj(int outT, const float* __restrict__ h2b,
                                        const float* __restrict__ Wproj,
                                        float* __restrict__ out) {
    const int tid = threadIdx.x;
    if (tid >= 160) return;
    int o = blockIdx.x * 40 + (tid >> 2);
    int part = tid & 3;
    int b = o / 80, m = o - b * 80;
    const float* hp = h2b + b * 1024 + part * 256;
    const float* wp = Wproj + (size_t)m * PROJK + part * 256;
    float v = 0.f, v2 = 0.f;
#pragma unroll 8
    for (int k = 0; k < 256; k += 8) {
        float4 h4 = *(const float4*)&hp[k];     float4 w4 = *(const float4*)&wp[k];
        float4 h5 = *(const float4*)&hp[k + 4]; float4 w5 = *(const float4*)&wp[k + 4];
        v  += h4.x * w4.x + h4.y * w4.y + h4.z * w4.z + h4.w * w4.w;
        v2 += h5.x * w5.x + h5.y * w5.y + h5.z * w5.z + h5.w * w5.w;
    }
    v += v2;
    v += __shfl_xor_sync(0xffffffffu, v, 1);
    v += __shfl_xor_sync(0xffffffffu, v, 2);
    if (part == 0)
        out[(size_t)(b * 80 + m) * 600 + outT] =
            v + d_PD[((size_t)outT * 64 + b) * 80 + m];
}

// ---------------------------------------------------------------------------
// Sequential persistent kernel — tf32 mma + 3-stage cp.async (k=64 slabs)
// CTA owns 32 gate cols: n in [0,32), gate = n>>3, wrow = (gate<<10)+c0+(n&7)
// warp w: batch tile m0 = 16*(w&3), gate-col tile n0 = 16*(w>>2)
// ---------------------------------------------------------------------------
__global__ void __launch_bounds__(256, 1) seq_kernel(
        const float* __restrict__ Whh1,
        const float* __restrict__ Wih2,
        const float* __restrict__ Whh2,
        const float* __restrict__ bih2,
        const float* __restrict__ bhh2,
        const float* __restrict__ Wproj,
        float* __restrict__ out) {
    extern __shared__ float sm[];
    float* Gs = sm + 3 * SLABF;            // [32][65]

    const int tid  = threadIdx.x;
    const int lane = tid & 31, w = tid >> 5;
    const int gi = lane >> 2, ti = lane & 3;
    const int cta = blockIdx.x;
    const int c0 = cta * 8;
    const int m0 = (w & 3) * 16;
    const int n0 = (w >> 2) * 16;

    // bias2 for this thread's 4 distinct n-cols
    float b2v[4];
#pragma unroll
    for (int q = 0; q < 4; q++) {
        int n = n0 + (q >> 1) * 8 + 2 * ti + (q & 1);
        int wr = ((n >> 3) << 10) + c0 + (n & 7);
        b2v[q] = bih2[wr] + bhh2[wr];
    }

    auto issue = [&](int st, const float* Ag, const float* Wg, int k0) {
        float* A = sm + st * SLABF;
        float* B = A + 64 * ARS;
#pragma unroll
        for (int i = 0; i < 4; i++) {
            int ch = tid + 256 * i;
            int r = ch >> 4, cq = (ch & 15) * 4;
            cp16(saddr(&A[r * ARS + cq]), Ag + (size_t)r * RNN + k0 + cq);
        }
#pragma unroll
        for (int i = 0; i < 2; i++) {
            int ch = tid + 256 * i;
            int n = ch >> 4, cq = (ch & 15) * 4;
            int wr = ((n >> 3) << 10) + c0 + (n & 7);
            cp16(saddr(&B[n * ARS + cq]), Wg + (size_t)wr * RNN + k0 + cq);
        }
        CP_COMMIT();
    };

    auto compute = [&](int st, float (*acc)[4]) {
        const float* A = sm + st * SLABF;
        const float* B = A + 64 * ARS;
#pragma unroll
        for (int kk = 0; kk < 64; kk += 8) {
            const float* ap = &A[(m0 + gi) * ARS + kk + ti];
            uint32_t a0 = cvt_tf32(ap[0]);
            uint32_t a1 = cvt_tf32(ap[8 * ARS]);
            uint32_t a2 = cvt_tf32(ap[4]);
            uint32_t a3 = cvt_tf32(ap[8 * ARS + 4]);
#pragma unroll
            for (int nt = 0; nt < 2; nt++) {
                const float* bp = &B[(n0 + nt * 8 + gi) * ARS + kk + ti];
                uint32_t b0 = cvt_tf32(bp[0]), b1 = cvt_tf32(bp[4]);
                mma_tf32(acc[nt][0], acc[nt][1], acc[nt][2], acc[nt][3],
                         a0, a1, a2, a3, b0, b1);
            }
        }
    };

    auto gemm16 = [&](const float* Ag, const float* Wg, float (*acc)[4]) {
        issue(0, Ag, Wg, 0);
        issue(1, Ag, Wg, 64);
        for (int i = 0; i < 16; i++) {
            if (i + 2 < 16) issue((i + 2) % 3, Ag, Wg, (i + 2) * 64);
            if (i < 14)       asm volatile("cp.async.wait_group 2;\n");
            else if (i == 14) asm volatile("cp.async.wait_group 1;\n");
            else              asm volatile("cp.async.wait_group 0;\n");
            __syncthreads();
            compute(i % 3, acc);
            __syncthreads();
        }
    };

    // zero initial state
    for (int i = cta * 256 + tid; i < BATCH * RNN; i += NCTA * 256) {
        d_h1[0][i] = 0.f; d_h2[0][i] = 0.f; d_c1[i] = 0.f; d_c2[i] = 0.f;
    }
    grid_barrier();

    for (int t = 0; t < TSTEPS; t++) {
        const int pb = t & 1, nb = pb ^ 1;

        if (t > 0) do_proj(t - 1, d_h2[pb], Wproj, out);

        // prefetch this thread's 8 G1 addends (latency hides under the GEMM)
        float g1v[8];
        {
            const float* g1p = d_G1 + (size_t)t * 64 * NG;
#pragma unroll
            for (int q = 0; q < 8; q++) {
                int nt = q >> 2, d = q & 3;
                int n = n0 + nt * 8 + 2 * ti + (d & 1);
                int m = m0 + gi + 8 * (d >> 1);
                int wr = ((n >> 3) << 10) + c0 + (n & 7);
                g1v[q] = g1p[(size_t)m * NG + wr];
            }
        }

        // ---- LSTM1: gates = G1[t] + h1_prev @ Whh1^T ----
        float acc[2][4] = {};
        gemm16(d_h1[pb], Whh1, acc);
#pragma unroll
        for (int q = 0; q < 8; q++) {
            int nt = q >> 2, d = q & 3;
            int n = n0 + nt * 8 + 2 * ti + (d & 1);
            int m = m0 + gi + 8 * (d >> 1);
            Gs[n * 65 + m] = acc[nt][d] + g1v[q];
        }
        __syncthreads();
#pragma unroll
        for (int s = 0; s < 2; s++) {
            int id = tid + s * 256;
            int uc = id >> 6, b = id & 63;
            float gI = Gs[uc * 65 + b];
            float gF = Gs[(8 + uc) * 65 + b];
            float gG = Gs[(16 + uc) * 65 + b];
            float gO = Gs[(24 + uc) * 65 + b];
            int ci = b * RNN + c0 + uc;
            float c = d_c1[ci];
            float cn = sigf(gF) * c + sigf(gI) * tanhf(gG);
            d_c1[ci] = cn;
            d_h1[nb][ci] = sigf(gO) * tanhf(cn);
        }
        grid_barrier();

        // ---- LSTM2: gates = h1 @ Wih2^T + h2_prev @ Whh2^T + b ----
        float acc2[2][4] = {};
        gemm16(d_h1[nb], Wih2, acc2);
        gemm16(d_h2[pb], Whh2, acc2);
#pragma unroll
        for (int q = 0; q < 8; q++) {
            int nt = q >> 2, d = q & 3;
            int n = n0 + nt * 8 + 2 * ti + (d & 1);
            int m = m0 + gi + 8 * (d >> 1);
            Gs[n * 65 + m] = acc2[nt][d] + b2v[nt * 2 + (d & 1)];
        }
        __syncthreads();
#pragma unroll
        for (int s = 0; s < 2; s++) {
            int id = tid + s * 256;
            int uc = id >> 6, b = id & 63;
            float gI = Gs[uc * 65 + b];
            float gF = Gs[(8 + uc) * 65 + b];
            float gG = Gs[(16 + uc) * 65 + b];
            float gO = Gs[(24 + uc) * 65 + b];
            int ci = b * RNN + c0 + uc;
            float c = d_c2[ci];
            float cn = sigf(gF) * c + sigf(gI) * tanhf(gG);
            d_c2[ci] = cn;
            d_h2[nb][ci] = sigf(gO) * tanhf(cn);
        }
        grid_barrier();
    }

    // final step's projection (h2(599) lives in buffer 0)
    do_proj(TSTEPS - 1, d_h2[0], Wproj, out);
}

// ---------------------------------------------------------------------------
// Launch (no static state — rule-compliant; setattr is idempotent)
// ---------------------------------------------------------------------------
extern "C" void kernel_launch(void* const* d_in, const int* in_sizes, int n_in,
                              void* d_out, int out_size) {
    (void)in_sizes; (void)n_in; (void)out_size;
    const float* dur   = (const float*)d_in[0];
    const float* dec   = (const float*)d_in[1];
    const float* Wp1   = (const float*)d_in[3];
    const float* Wp2   = (const float*)d_in[4];
    const float* Wih1  = (const float*)d_in[5];
    const float* Whh1  = (const float*)d_in[6];
    const float* bih1  = (const float*)d_in[7];
    const float* bhh1  = (const float*)d_in[8];
    const float* Wih2  = (const float*)d_in[9];
    const float* Whh2  = (const float*)d_in[10];
    const float* bih2  = (const float*)d_in[11];
    const float* bhh2  = (const float*)d_in[12];
    const float* Wproj = (const float*)d_in[13];
    const float* bproj = (const float*)d_in[14];
    float* out = (float*)d_out;

    // Partitionable (foldlike) split of jax.random.key(42) = (0, 42)
    uint32_t d1a = 0u, d1b = 0u; tf2x32(0u, 42u, d1a, d1b);   // child 0
    uint32_t d2a = 0u, d2b = 1u; tf2x32(0u, 42u, d2a, d2b);   // child 1

    cudaFuncSetAttribute(seq_kernel,
                         cudaFuncAttributeMaxDynamicSharedMemorySize,
                         SEQ_SMEM_BYTES);

    prenet_kernel<<<dim3(8, 600), 256>>>(dec, Wp1, Wp2, d1a, d1b, d2a, d2b);
    build_x_kernel<<<(NROWS * ENCPOS + 255) / 256, 256>>>(dur);
    projdur_kernel<<<(NROWS * NMEL + 255) / 256, 256>>>(dur, Wproj, bproj);
    gemm_g1_mma<<<dim3(NG / 128, NROWS / 128), 256>>>(Wih1, bih1, bhh1);
    seq_kernel<<<NCTA, 256, SEQ_SMEM_BYTES>>>(Whh1, Wih2, Whh2, bih2, bhh2,
                                              Wproj, out);
}